// round 1
// baseline (speedup 1.0000x reference)
#include <cuda_runtime.h>
#include <math.h>

// ---------------------------------------------------------------------------
// HardThresholdingAttentionalDecoder — output-sparse restructuring.
// B=4, S=2048, H=1024, heads=8, d=128, C=1000.
// Only position-0 queries matter for both outputs, so:
//   - K/V: one fused 8192x2048x1024 SGEMM with algebraically combined weights
//   - Q: position 0 only (tiny GEMVs)
//   - attention: 1 query row per (b,h)
//   - out_proj / LN / fc: position 0 only
// Output layout assumed: [logits (4*1000) | cls_attn_weights (4*8*2048)].
// ---------------------------------------------------------------------------

#define BM 128
#define BN 128
#define BK 16

// Scratch (device globals; no allocation allowed in kernel_launch)
__device__ float g_WT[2u * 1024u * 1024u];     // [Wk^T ; Wv^T]
__device__ float g_Wc[2u * 1024u * 1024u];     // combined K/V weights (2048 x 1024)
__device__ float g_bc[2048];                   // combined K/V bias
__device__ float g_KV[8192u * 2048u];          // [K feats | V feats] per row
__device__ float g_tmp[4 * 1024];              // q chain intermediate
__device__ float g_q0[4 * 1024];               // q at position 0
__device__ float g_attn0[4 * 1024];            // attention output at position 0
__device__ float g_y[4 * 1024];                // out_proj + residual
__device__ float g_cls[4 * 1024];              // layernormed cls token

// --------------------------- warp/block reduce -----------------------------
__device__ __forceinline__ float warpSum(float v) {
    #pragma unroll
    for (int o = 16; o; o >>= 1) v += __shfl_xor_sync(0xffffffffu, v, o);
    return v;
}
__device__ __forceinline__ float warpMax(float v) {
    #pragma unroll
    for (int o = 16; o; o >>= 1) v = fmaxf(v, __shfl_xor_sync(0xffffffffu, v, o));
    return v;
}

// --------------------------- transpose Wk, Wv ------------------------------
__global__ void transpose_kernel(const float* __restrict__ Wk,
                                 const float* __restrict__ Wv) {
    __shared__ float tile[32][33];
    const float* src = (blockIdx.z == 0) ? Wk : Wv;
    float* dst = g_WT + (size_t)blockIdx.z * 1024u * 1024u;
    int x = blockIdx.x * 32 + threadIdx.x;
    int y = blockIdx.y * 32 + threadIdx.y;
    #pragma unroll
    for (int i = 0; i < 32; i += 8)
        tile[threadIdx.y + i][threadIdx.x] = src[(size_t)(y + i) * 1024 + x];
    __syncthreads();
    x = blockIdx.y * 32 + threadIdx.x;
    y = blockIdx.x * 32 + threadIdx.y;
    #pragma unroll
    for (int i = 0; i < 32; i += 8)
        dst[(size_t)(y + i) * 1024 + x] = tile[threadIdx.x][threadIdx.y + i];
}

// --------------------------- SGEMM: C = A * B^T + bias ---------------------
// A: M x K row-major, B: N x K row-major (both K-contiguous), C: M x N.
// 256 threads, 128x128 tile, 8x8 per thread.
__global__ __launch_bounds__(256) void sgemm_nt(
    const float* __restrict__ A, const float* __restrict__ B,
    const float* __restrict__ bias, float* __restrict__ C,
    int M, int N, int K) {
    __shared__ float As[BK][BM];
    __shared__ float Bs[BK][BN];
    const int bm = blockIdx.y * BM;
    const int bn = blockIdx.x * BN;
    const int tid = threadIdx.x;
    const int tx = tid & 15;   // 16 cols of threads
    const int ty = tid >> 4;   // 16 rows of threads

    float acc[8][8];
    #pragma unroll
    for (int i = 0; i < 8; i++)
        #pragma unroll
        for (int j = 0; j < 8; j++) acc[i][j] = 0.f;

    for (int k0 = 0; k0 < K; k0 += BK) {
        #pragma unroll
        for (int t = 0; t < 2; t++) {
            int e = tid + t * 256;       // float4 id: 512 per tile
            int row = e >> 2;
            int kq = e & 3;
            float4 va = *(const float4*)(A + (size_t)(bm + row) * K + k0 + kq * 4);
            As[kq * 4 + 0][row] = va.x;
            As[kq * 4 + 1][row] = va.y;
            As[kq * 4 + 2][row] = va.z;
            As[kq * 4 + 3][row] = va.w;
            float4 vb = *(const float4*)(B + (size_t)(bn + row) * K + k0 + kq * 4);
            Bs[kq * 4 + 0][row] = vb.x;
            Bs[kq * 4 + 1][row] = vb.y;
            Bs[kq * 4 + 2][row] = vb.z;
            Bs[kq * 4 + 3][row] = vb.w;
        }
        __syncthreads();
        #pragma unroll
        for (int k = 0; k < BK; k++) {
            float a[8], b[8];
            #pragma unroll
            for (int i = 0; i < 8; i++) a[i] = As[k][ty * 8 + i];
            #pragma unroll
            for (int j = 0; j < 8; j++) b[j] = Bs[k][tx * 8 + j];
            #pragma unroll
            for (int i = 0; i < 8; i++)
                #pragma unroll
                for (int j = 0; j < 8; j++) acc[i][j] = fmaf(a[i], b[j], acc[i][j]);
        }
        __syncthreads();
    }

    #pragma unroll
    for (int i = 0; i < 8; i++) {
        int m = bm + ty * 8 + i;
        #pragma unroll
        for (int j = 0; j < 8; j++) {
            int n = bn + tx * 8 + j;
            float v = acc[i][j];
            if (bias) v += bias[n];
            C[(size_t)m * N + n] = v;
        }
    }
}

// --------------------------- GEMV (warp per output) ------------------------
// C[r, o] = dot(A[r*strideA : +K], W[o*K : +K]) + bias[o] + resid[r*strideR + o]
__global__ __launch_bounds__(256) void gemv_nt(
    const float* __restrict__ A, long long strideA,
    const float* __restrict__ W,
    const float* __restrict__ bias,
    const float* __restrict__ resid, long long strideR,
    float* __restrict__ C, int O, int K) {
    int r = blockIdx.y;
    int warp = threadIdx.x >> 5, lane = threadIdx.x & 31;
    int o = blockIdx.x * 8 + warp;
    if (o >= O) return;
    const float* a = A + (size_t)r * strideA;
    const float* w = W + (size_t)o * K;
    float acc = 0.f;
    for (int k = lane * 4; k < K; k += 128) {
        float4 av = *(const float4*)(a + k);
        float4 wv = *(const float4*)(w + k);
        acc += av.x * wv.x + av.y * wv.y + av.z * wv.z + av.w * wv.w;
    }
    acc = warpSum(acc);
    if (lane == 0) {
        float v = acc;
        if (bias) v += bias[o];
        if (resid) v += resid[(size_t)r * strideR + o];
        C[(size_t)r * O + o] = v;
    }
}

// --------------------------- attention for query 0 -------------------------
// grid (8 heads, 4 batches), 256 threads. Writes thresholded+renormed weights
// to w_out and the attention output for position 0 to g_attn0.
__global__ __launch_bounds__(256) void attn_cls_kernel(
    const int* __restrict__ mask, float* __restrict__ w_out) {
    const int b = blockIdx.y, h = blockIdx.x;
    const int tid = threadIdx.x, warp = tid >> 5, lane = tid & 31;
    __shared__ float sq[128];
    __shared__ float sw[2048];
    __shared__ float red[8];

    if (tid < 128) sq[tid] = g_q0[b * 1024 + h * 128 + tid];
    __syncthreads();

    const float scale = 0.08838834764831845f;  // 1/sqrt(128)
    for (int s = warp; s < 2048; s += 8) {
        const float* krow = g_KV + (size_t)(b * 2048 + s) * 2048 + h * 128;
        float4 kv = *(const float4*)(krow + lane * 4);
        float4 qv = *(const float4*)(sq + lane * 4);
        float acc = kv.x * qv.x + kv.y * qv.y + kv.z * qv.z + kv.w * qv.w;
        acc = warpSum(acc);
        if (lane == 0) {
            float sc = acc * scale;
            if (mask[b * 2048 + s] == 0) sc = -1e9f;
            sw[s] = sc;
        }
    }
    __syncthreads();

    // block max
    float m = -3.4e38f;
    for (int i = tid; i < 2048; i += 256) m = fmaxf(m, sw[i]);
    m = warpMax(m);
    if (lane == 0) red[warp] = m;
    __syncthreads();
    float bmax = red[0];
    #pragma unroll
    for (int i = 1; i < 8; i++) bmax = fmaxf(bmax, red[i]);
    __syncthreads();

    // exp + block sum
    float sum = 0.f;
    for (int i = tid; i < 2048; i += 256) {
        float e = expf(sw[i] - bmax);
        sw[i] = e;
        sum += e;
    }
    sum = warpSum(sum);
    if (lane == 0) red[warp] = sum;
    __syncthreads();
    float S = 0.f;
    #pragma unroll
    for (int i = 0; i < 8; i++) S += red[i];
    __syncthreads();

    // normalize, hard-threshold, re-sum
    float s2 = 0.f;
    for (int i = tid; i < 2048; i += 256) {
        float wv = sw[i] / S;
        wv = (wv < 0.001f) ? 0.f : wv;
        sw[i] = wv;
        s2 += wv;
    }
    s2 = warpSum(s2);
    if (lane == 0) red[warp] = s2;
    __syncthreads();
    float S2 = 0.f;
    #pragma unroll
    for (int i = 0; i < 8; i++) S2 += red[i];
    float denom = S2 + 1e-9f;

    for (int i = tid; i < 2048; i += 256) {
        float wv = sw[i] / denom;
        sw[i] = wv;
        w_out[(size_t)(b * 8 + h) * 2048 + i] = wv;
    }
    __syncthreads();

    // out0[d] = sum_s w[s] * V[b, s, h*128 + d]
    if (tid < 128) {
        const float* vbase = g_KV + (size_t)b * 2048 * 2048 + 1024 + h * 128 + tid;
        float acc = 0.f;
        for (int s = 0; s < 2048; s++) acc = fmaf(sw[s], vbase[(size_t)s * 2048], acc);
        g_attn0[b * 1024 + h * 128 + tid] = acc;
    }
}

// --------------------------- layernorm on cls token ------------------------
__global__ __launch_bounds__(256) void ln_kernel(const float* __restrict__ gamma,
                                                 const float* __restrict__ beta) {
    const int b = blockIdx.x, tid = threadIdx.x;
    const int warp = tid >> 5, lane = tid & 31;
    __shared__ float red[8];

    float sum = 0.f;
    for (int i = tid; i < 1024; i += 256) sum += g_y[b * 1024 + i];
    sum = warpSum(sum);
    if (lane == 0) red[warp] = sum;
    __syncthreads();
    float tot = 0.f;
    #pragma unroll
    for (int i = 0; i < 8; i++) tot += red[i];
    float mu = tot * (1.f / 1024.f);
    __syncthreads();

    float vs = 0.f;
    for (int i = tid; i < 1024; i += 256) {
        float d = g_y[b * 1024 + i] - mu;
        vs += d * d;
    }
    vs = warpSum(vs);
    if (lane == 0) red[warp] = vs;
    __syncthreads();
    float vtot = 0.f;
    #pragma unroll
    for (int i = 0; i < 8; i++) vtot += red[i];
    float var = vtot * (1.f / 1024.f);
    float inv = 1.0f / sqrtf(var + 1e-5f);

    for (int i = tid; i < 1024; i += 256) {
        float xn = (g_y[b * 1024 + i] - mu) * inv * gamma[i] + beta[i];
        g_cls[b * 1024 + i] = xn;
    }
}

// ---------------------------------------------------------------------------
extern "C" void kernel_launch(void* const* d_in, const int* in_sizes, int n_in,
                              void* d_out, int out_size) {
    const float* enc  = (const float*)d_in[0];   // (4, 2048, 1024)
    const int*   mask = (const int*)  d_in[1];   // (4, 2048)
    const float* Wq   = (const float*)d_in[2];
    const float* bq   = (const float*)d_in[3];
    const float* Wk   = (const float*)d_in[4];
    // d_in[5] = bk, d_in[7] = bv used below
    const float* bk   = (const float*)d_in[5];
    const float* Wv   = (const float*)d_in[6];
    const float* bv   = (const float*)d_in[7];
    const float* ipw  = (const float*)d_in[8];   // (3072, 1024): [wiq; wik; wiv]
    const float* ipb  = (const float*)d_in[9];   // (3072,)
    const float* opw  = (const float*)d_in[10];
    const float* opb  = (const float*)d_in[11];
    const float* lng  = (const float*)d_in[12];
    const float* lnb  = (const float*)d_in[13];
    const float* fcw  = (const float*)d_in[14];
    const float* fcb  = (const float*)d_in[15];
    float* out = (float*)d_out;                  // [logits 4000 | weights 65536]

    float *pWT, *pWc, *pbc, *pKV, *ptmp, *pq0, *pattn0, *py, *pcls;
    cudaGetSymbolAddress((void**)&pWT,    g_WT);
    cudaGetSymbolAddress((void**)&pWc,    g_Wc);
    cudaGetSymbolAddress((void**)&pbc,    g_bc);
    cudaGetSymbolAddress((void**)&pKV,    g_KV);
    cudaGetSymbolAddress((void**)&ptmp,   g_tmp);
    cudaGetSymbolAddress((void**)&pq0,    g_q0);
    cudaGetSymbolAddress((void**)&pattn0, g_attn0);
    cudaGetSymbolAddress((void**)&py,     g_y);
    cudaGetSymbolAddress((void**)&pcls,   g_cls);

    // 1) Wk^T, Wv^T
    transpose_kernel<<<dim3(32, 32, 2), dim3(32, 8)>>>(Wk, Wv);

    // 2) combined K/V weights: Wck = wik @ Wk, Wcv = wiv @ Wv  (NT form via W^T)
    sgemm_nt<<<dim3(8, 8), 256>>>(ipw + 1024 * 1024, pWT, nullptr,
                                  pWc, 1024, 1024, 1024);
    sgemm_nt<<<dim3(8, 8), 256>>>(ipw + 2048 * 1024, pWT + 1024 * 1024, nullptr,
                                  pWc + 1024 * 1024, 1024, 1024, 1024);

    // 3) combined biases: bck = wik@bk + bik, bcv = wiv@bv + biv
    gemv_nt<<<dim3(128, 1), 256>>>(bk, 0, ipw + 1024 * 1024, ipb + 1024,
                                   nullptr, 0, pbc, 1024, 1024);
    gemv_nt<<<dim3(128, 1), 256>>>(bv, 0, ipw + 2048 * 1024, ipb + 2048,
                                   nullptr, 0, pbc + 1024, 1024, 1024);

    // 4) main GEMM: KV = X @ Wc^T + bc   (8192 x 2048 x 1024)
    sgemm_nt<<<dim3(16, 64), 256>>>(enc, pWc, pbc, pKV, 8192, 2048, 1024);

    // 5) q at position 0: two chained small projections
    gemv_nt<<<dim3(128, 4), 256>>>(enc, 2048LL * 1024, Wq, bq,
                                   nullptr, 0, ptmp, 1024, 1024);
    gemv_nt<<<dim3(128, 4), 256>>>(ptmp, 1024, ipw, ipb,
                                   nullptr, 0, pq0, 1024, 1024);

    // 6) attention for query 0 (writes cls weights + attn output)
    attn_cls_kernel<<<dim3(8, 4), 256>>>(mask, out + 4000);

    // 7) out_proj + residual at position 0
    gemv_nt<<<dim3(128, 4), 256>>>(pattn0, 1024, opw, opb,
                                   enc, 2048LL * 1024, py, 1024, 1024);

    // 8) layernorm
    ln_kernel<<<4, 256>>>(lng, lnb);

    // 9) classifier head -> logits
    gemv_nt<<<dim3(125, 4), 256>>>(pcls, 1024, fcw, fcb,
                                   nullptr, 0, out, 1000, 1024);
}

// round 2
// speedup vs baseline: 16.4153x; 16.4153x over previous
#include <cuda_runtime.h>
#include <math.h>

// ---------------------------------------------------------------------------
// HardThresholdingAttentionalDecoder — fully output-sparse + linearity-folded.
// B=4, S=2048, H=1024, heads=8, d=128, C=1000.
// K and V are NEVER materialized:
//   scores[b,h,s] = (t[b,h,:]·X[b,s,:] + q0·bck_h) / sqrt(d),
//     t[b,h,:] = (q0_h · wik_h) @ Wk
//   attn_out[b,h] = ((Σ_s w·X[b,s,:]) @ Wv^T) @ wiv_h^T + (Σw)·bcv_h
// Output layout: [logits (4*1000) | cls_attn_weights (4*8*2048)].
// ---------------------------------------------------------------------------

// Scratch (device globals; no allocation allowed)
__device__ float g_WkT[1024u * 1024u];     // Wk^T
__device__ float g_tmp[4 * 1024];          // q chain intermediate
__device__ float g_q0[4 * 1024];           // q at position 0
__device__ float g_u[32 * 1024];           // u[b,h,:] = q0_h · wik_h
__device__ float g_t[32 * 1024];           // t[b,h,:] = u @ Wk
__device__ float g_bck[1024];              // wik@bk + bik
__device__ float g_bcv[1024];              // wiv@bv + biv
__device__ float g_sbias[32];              // q0_h · bck_h
__device__ float g_scores[32 * 2048];      // masked scaled scores
__device__ float g_sumw[32];               // sum of final weights
__device__ float g_rpart[8 * 32 * 1024];   // partial weighted sums of X
__device__ float g_r[32 * 1024];           // r[b,h,:] = sum_s w*X
__device__ float g_p[32 * 1024];           // p = r @ Wv^T
__device__ float g_attn0[4 * 1024];        // attention output at position 0
__device__ float g_y[4 * 1024];            // out_proj + residual
__device__ float g_cls[4 * 1024];          // layernormed cls token

// --------------------------- warp reduce ------------------------------------
__device__ __forceinline__ float warpSum(float v) {
    #pragma unroll
    for (int o = 16; o; o >>= 1) v += __shfl_xor_sync(0xffffffffu, v, o);
    return v;
}
__device__ __forceinline__ float warpMax(float v) {
    #pragma unroll
    for (int o = 16; o; o >>= 1) v = fmaxf(v, __shfl_xor_sync(0xffffffffu, v, o));
    return v;
}
__device__ __forceinline__ float dot4(float4 a, float4 b) {
    return a.x * b.x + a.y * b.y + a.z * b.z + a.w * b.w;
}

// --------------------------- transpose Wk -----------------------------------
__global__ void transpose_k(const float* __restrict__ src) {
    __shared__ float tile[32][33];
    int x = blockIdx.x * 32 + threadIdx.x;
    int y = blockIdx.y * 32 + threadIdx.y;
    #pragma unroll
    for (int i = 0; i < 32; i += 8)
        tile[threadIdx.y + i][threadIdx.x] = src[(size_t)(y + i) * 1024 + x];
    __syncthreads();
    x = blockIdx.y * 32 + threadIdx.x;
    y = blockIdx.x * 32 + threadIdx.y;
    #pragma unroll
    for (int i = 0; i < 32; i += 8)
        g_WkT[(size_t)(y + i) * 1024 + x] = tile[threadIdx.x][threadIdx.y + i];
}

// --------------------------- block-per-output GEMV --------------------------
// C[r*O + o] = dot(A[r*strideA : +K], W[o*K : +K]) + bias[o] + resid[r*strideR+o]
// grid (O, R), block 256. K multiple of 4.
__global__ __launch_bounds__(256) void gemv_block(
    const float* __restrict__ A, long long strideA,
    const float* __restrict__ W,
    const float* __restrict__ bias,
    const float* __restrict__ resid, long long strideR,
    float* __restrict__ C, int K) {
    const int o = blockIdx.x, r = blockIdx.y, O = gridDim.x;
    const float* a = A + (size_t)r * strideA;
    const float* w = W + (size_t)o * K;
    float acc = 0.f;
    for (int k = threadIdx.x * 4; k < K; k += 1024) {
        float4 av = *(const float4*)(a + k);
        float4 wv = *(const float4*)(w + k);
        acc += dot4(av, wv);
    }
    acc = warpSum(acc);
    __shared__ float red[8];
    if ((threadIdx.x & 31) == 0) red[threadIdx.x >> 5] = acc;
    __syncthreads();
    if (threadIdx.x == 0) {
        float s = 0.f;
        #pragma unroll
        for (int i = 0; i < 8; i++) s += red[i];
        if (bias) s += bias[o];
        if (resid) s += resid[(size_t)r * strideR + o];
        C[(size_t)r * O + o] = s;
    }
}

// --------------------------- u[b,h,:] = q0_h · wik_h ------------------------
// grid (4 ctiles, 8 heads), block 256.
__global__ __launch_bounds__(256) void u_kernel(const float* __restrict__ wik) {
    const int h = blockIdx.y, tid = threadIdx.x;
    __shared__ float sq[4][128];
    for (int idx = tid; idx < 512; idx += 256) {
        int b = idx >> 7, i = idx & 127;
        sq[b][i] = g_q0[b * 1024 + h * 128 + i];
    }
    __syncthreads();
    const int c = blockIdx.x * 256 + tid;
    float acc[4] = {0.f, 0.f, 0.f, 0.f};
    #pragma unroll 4
    for (int i = 0; i < 128; i++) {
        float wv = wik[(size_t)(h * 128 + i) * 1024 + c];
        #pragma unroll
        for (int b = 0; b < 4; b++) acc[b] += sq[b][i] * wv;
    }
    #pragma unroll
    for (int b = 0; b < 4; b++) g_u[(b * 8 + h) * 1024 + c] = acc[b];
}

// --------------------------- C[32,1024] = A[32,1024] @ W[1024,1024]^T -------
// grid 128 (8 outputs/block), block 256.
__global__ __launch_bounds__(256) void nt32(
    const float* __restrict__ A, const float* __restrict__ W,
    float* __restrict__ C) {
    __shared__ float sA[32][256];
    const int tid = threadIdx.x, warp = tid >> 5, lane = tid & 31;
    const int o = blockIdx.x * 8 + warp;
    float acc[32];
    #pragma unroll
    for (int r = 0; r < 32; r++) acc[r] = 0.f;

    for (int k0 = 0; k0 < 1024; k0 += 256) {
        for (int idx = tid * 4; idx < 32 * 256; idx += 1024) {
            int r = idx >> 8, kk = idx & 255;
            *(float4*)&sA[r][kk] = *(const float4*)&A[r * 1024 + k0 + kk];
        }
        __syncthreads();
        #pragma unroll
        for (int t = 0; t < 2; t++) {
            float4 w4 = *(const float4*)&W[(size_t)o * 1024 + k0 + t * 128 + lane * 4];
            #pragma unroll
            for (int r = 0; r < 32; r++) {
                float4 a4 = *(const float4*)&sA[r][t * 128 + lane * 4];
                acc[r] += dot4(a4, w4);
            }
        }
        __syncthreads();
    }
    #pragma unroll
    for (int r = 0; r < 32; r++) {
        float s = warpSum(acc[r]);
        if (lane == 0) C[r * 1024 + o] = s;
    }
}

// --------------------------- sbias[b,h] = q0_h · bck_h ----------------------
__global__ __launch_bounds__(256) void sbias_kernel() {
    const int warp = threadIdx.x >> 5, lane = threadIdx.x & 31;
    for (int idx = warp; idx < 32; idx += 8) {
        int b = idx >> 3, h = idx & 7;
        float4 q = *(const float4*)&g_q0[b * 1024 + h * 128 + lane * 4];
        float4 c = *(const float4*)&g_bck[h * 128 + lane * 4];
        float s = warpSum(dot4(q, c));
        if (lane == 0) g_sbias[idx] = s;
    }
}

// --------------------------- scores pass over X -----------------------------
// grid (64, 4 batches), block 256 (8 warps x 4 s each).
__global__ __launch_bounds__(256) void scores_kernel(
    const float* __restrict__ X, const int* __restrict__ mask) {
    __shared__ float sT[8][1024];
    const int b = blockIdx.y, tid = threadIdx.x, warp = tid >> 5, lane = tid & 31;
    for (int idx = tid * 4; idx < 8192; idx += 1024) {
        int h = idx >> 10, c = idx & 1023;
        *(float4*)&sT[h][c] = *(const float4*)&g_t[(b * 8 + h) * 1024 + c];
    }
    __syncthreads();
    const int s0 = blockIdx.x * 32 + warp * 4;
    const float* xb = X + (size_t)b * 2048 * 1024;
    float acc[4][8];
    #pragma unroll
    for (int si = 0; si < 4; si++)
        #pragma unroll
        for (int h = 0; h < 8; h++) acc[si][h] = 0.f;

    #pragma unroll
    for (int it = 0; it < 8; it++) {
        float4 t4[8];
        #pragma unroll
        for (int h = 0; h < 8; h++) t4[h] = *(const float4*)&sT[h][it * 128 + lane * 4];
        #pragma unroll
        for (int si = 0; si < 4; si++) {
            float4 x4 = *(const float4*)&xb[(size_t)(s0 + si) * 1024 + it * 128 + lane * 4];
            #pragma unroll
            for (int h = 0; h < 8; h++) acc[si][h] += dot4(x4, t4[h]);
        }
    }
    const float scale = 0.08838834764831845f;  // 1/sqrt(128)
    #pragma unroll
    for (int si = 0; si < 4; si++) {
        #pragma unroll
        for (int h = 0; h < 8; h++) {
            float v = warpSum(acc[si][h]);
            if (lane == 0) {
                int s = s0 + si;
                float sc = (v + g_sbias[b * 8 + h]) * scale;
                if (mask[b * 2048 + s] == 0) sc = -1e9f;
                g_scores[(b * 8 + h) * 2048 + s] = sc;
            }
        }
    }
}

// --------------------------- softmax + hard threshold -----------------------
// grid (8 heads, 4 batches), block 256.
__global__ __launch_bounds__(256) void softmax_kernel(float* __restrict__ w_out) {
    const int b = blockIdx.y, h = blockIdx.x;
    const int tid = threadIdx.x, warp = tid >> 5, lane = tid & 31;
    __shared__ float sw[2048];
    __shared__ float red[8];
    const size_t row = (size_t)(b * 8 + h) * 2048;

    for (int i = tid; i < 2048; i += 256) sw[i] = g_scores[row + i];
    __syncthreads();

    float m = -3.4e38f;
    for (int i = tid; i < 2048; i += 256) m = fmaxf(m, sw[i]);
    m = warpMax(m);
    if (lane == 0) red[warp] = m;
    __syncthreads();
    float bmax = red[0];
    #pragma unroll
    for (int i = 1; i < 8; i++) bmax = fmaxf(bmax, red[i]);
    __syncthreads();

    float sum = 0.f;
    for (int i = tid; i < 2048; i += 256) {
        float e = expf(sw[i] - bmax);
        sw[i] = e;
        sum += e;
    }
    sum = warpSum(sum);
    if (lane == 0) red[warp] = sum;
    __syncthreads();
    float S = 0.f;
    #pragma unroll
    for (int i = 0; i < 8; i++) S += red[i];
    __syncthreads();

    float s2 = 0.f;
    for (int i = tid; i < 2048; i += 256) {
        float wv = sw[i] / S;
        wv = (wv < 0.001f) ? 0.f : wv;
        sw[i] = wv;
        s2 += wv;
    }
    s2 = warpSum(s2);
    if (lane == 0) red[warp] = s2;
    __syncthreads();
    float S2 = 0.f;
    #pragma unroll
    for (int i = 0; i < 8; i++) S2 += red[i];
    const float denom = S2 + 1e-9f;

    for (int i = tid; i < 2048; i += 256)
        w_out[row + i] = sw[i] / denom;
    if (tid == 0) g_sumw[b * 8 + h] = S2 / denom;
}

// --------------------------- weighted-sum pass over X -----------------------
// r_part[sc][b,h,c] = sum_{s in chunk sc} w[b,h,s] * X[b,s,c]
// grid (4 ctiles, 4 batches, 8 s-chunks), block 256.
__global__ __launch_bounds__(256) void wsum_kernel(
    const float* __restrict__ X, const float* __restrict__ w) {
    __shared__ float sW[8][256];
    const int b = blockIdx.y, sc = blockIdx.z, tid = threadIdx.x;
    const int c = blockIdx.x * 256 + tid;
    for (int idx = tid; idx < 2048; idx += 256) {
        int h = idx >> 8, ss = idx & 255;
        sW[h][ss] = w[(size_t)(b * 8 + h) * 2048 + sc * 256 + ss];
    }
    __syncthreads();
    float acc[8];
    #pragma unroll
    for (int h = 0; h < 8; h++) acc[h] = 0.f;
    const float* xb = X + (size_t)b * 2048 * 1024 + (size_t)sc * 256 * 1024 + c;
    #pragma unroll 4
    for (int ss = 0; ss < 256; ss++) {
        float x = xb[(size_t)ss * 1024];
        #pragma unroll
        for (int h = 0; h < 8; h++) acc[h] += sW[h][ss] * x;
    }
    #pragma unroll
    for (int h = 0; h < 8; h++)
        g_rpart[((size_t)sc * 32 + b * 8 + h) * 1024 + c] = acc[h];
}

// --------------------------- reduce partials --------------------------------
__global__ __launch_bounds__(256) void rreduce_kernel() {
    const int bh = blockIdx.x;
    const int c = threadIdx.x * 4;
    float4 s = {0.f, 0.f, 0.f, 0.f};
    #pragma unroll
    for (int sc = 0; sc < 8; sc++) {
        float4 v = *(const float4*)&g_rpart[((size_t)sc * 32 + bh) * 1024 + c];
        s.x += v.x; s.y += v.y; s.z += v.z; s.w += v.w;
    }
    *(float4*)&g_r[(size_t)bh * 1024 + c] = s;
}

// --------------------------- attn0 = p @ wiv_h^T + sumw*bcv -----------------
// grid 128 (8 outputs i per block), block 256.
__global__ __launch_bounds__(256) void attn_kernel(const float* __restrict__ wiv) {
    const int warp = threadIdx.x >> 5, lane = threadIdx.x & 31;
    const int i = blockIdx.x * 8 + warp;
    const int h = i >> 7;
    float acc[4] = {0.f, 0.f, 0.f, 0.f};
    #pragma unroll
    for (int it = 0; it < 8; it++) {
        float4 w4 = *(const float4*)&wiv[(size_t)i * 1024 + it * 128 + lane * 4];
        #pragma unroll
        for (int b = 0; b < 4; b++) {
            float4 p4 = *(const float4*)&g_p[(size_t)(b * 8 + h) * 1024 + it * 128 + lane * 4];
            acc[b] += dot4(p4, w4);
        }
    }
    #pragma unroll
    for (int b = 0; b < 4; b++) {
        float s = warpSum(acc[b]);
        if (lane == 0) g_attn0[b * 1024 + i] = s + g_sumw[b * 8 + h] * g_bcv[i];
    }
}

// --------------------------- layernorm on cls token -------------------------
__global__ __launch_bounds__(256) void ln_kernel(const float* __restrict__ gamma,
                                                 const float* __restrict__ beta) {
    const int b = blockIdx.x, tid = threadIdx.x;
    const int warp = tid >> 5, lane = tid & 31;
    __shared__ float red[8];

    float sum = 0.f;
    for (int i = tid; i < 1024; i += 256) sum += g_y[b * 1024 + i];
    sum = warpSum(sum);
    if (lane == 0) red[warp] = sum;
    __syncthreads();
    float tot = 0.f;
    #pragma unroll
    for (int i = 0; i < 8; i++) tot += red[i];
    float mu = tot * (1.f / 1024.f);
    __syncthreads();

    float vs = 0.f;
    for (int i = tid; i < 1024; i += 256) {
        float d = g_y[b * 1024 + i] - mu;
        vs += d * d;
    }
    vs = warpSum(vs);
    if (lane == 0) red[warp] = vs;
    __syncthreads();
    float vtot = 0.f;
    #pragma unroll
    for (int i = 0; i < 8; i++) vtot += red[i];
    float inv = 1.0f / sqrtf(vtot * (1.f / 1024.f) + 1e-5f);

    for (int i = tid; i < 1024; i += 256)
        g_cls[b * 1024 + i] = (g_y[b * 1024 + i] - mu) * inv * gamma[i] + beta[i];
}

// ---------------------------------------------------------------------------
extern "C" void kernel_launch(void* const* d_in, const int* in_sizes, int n_in,
                              void* d_out, int out_size) {
    const float* enc  = (const float*)d_in[0];   // (4, 2048, 1024)
    const int*   mask = (const int*)  d_in[1];   // (4, 2048)
    const float* Wq   = (const float*)d_in[2];
    const float* bq   = (const float*)d_in[3];
    const float* Wk   = (const float*)d_in[4];
    const float* bk   = (const float*)d_in[5];
    const float* Wv   = (const float*)d_in[6];
    const float* bv   = (const float*)d_in[7];
    const float* ipw  = (const float*)d_in[8];   // (3072, 1024): [wiq; wik; wiv]
    const float* ipb  = (const float*)d_in[9];
    const float* opw  = (const float*)d_in[10];
    const float* opb  = (const float*)d_in[11];
    const float* lng  = (const float*)d_in[12];
    const float* lnb  = (const float*)d_in[13];
    const float* fcw  = (const float*)d_in[14];
    const float* fcb  = (const float*)d_in[15];
    float* out = (float*)d_out;                  // [logits 4000 | weights 65536]

    const float* wik = ipw + 1024 * 1024;
    const float* wiv = ipw + 2048 * 1024;

    float *pWkT, *ptmp, *pq0, *pu, *pt, *pbck, *pbcv, *pr, *pp, *pattn0, *py, *pcls;
    cudaGetSymbolAddress((void**)&pWkT,   g_WkT);
    cudaGetSymbolAddress((void**)&ptmp,   g_tmp);
    cudaGetSymbolAddress((void**)&pq0,    g_q0);
    cudaGetSymbolAddress((void**)&pu,     g_u);
    cudaGetSymbolAddress((void**)&pt,     g_t);
    cudaGetSymbolAddress((void**)&pbck,   g_bck);
    cudaGetSymbolAddress((void**)&pbcv,   g_bcv);
    cudaGetSymbolAddress((void**)&pr,     g_r);
    cudaGetSymbolAddress((void**)&pp,     g_p);
    cudaGetSymbolAddress((void**)&pattn0, g_attn0);
    cudaGetSymbolAddress((void**)&py,     g_y);
    cudaGetSymbolAddress((void**)&pcls,   g_cls);

    float* w_out = out + 4000;

    // Wk^T (needed for t = u @ Wk as an NT product)
    transpose_k<<<dim3(32, 32), dim3(32, 8)>>>(Wk);

    // combined biases: bck = wik@bk + bik, bcv = wiv@bv + biv
    gemv_block<<<dim3(1024, 1), 256>>>(bk, 0, wik, ipb + 1024, nullptr, 0, pbck, 1024);
    gemv_block<<<dim3(1024, 1), 256>>>(bv, 0, wiv, ipb + 2048, nullptr, 0, pbcv, 1024);

    // q at position 0: two chained projections
    gemv_block<<<dim3(1024, 4), 256>>>(enc, 2048LL * 1024, Wq, bq, nullptr, 0, ptmp, 1024);
    gemv_block<<<dim3(1024, 4), 256>>>(ptmp, 1024, ipw, ipb, nullptr, 0, pq0, 1024);

    // u[b,h,:] = q0_h · wik_h ;  t = u @ Wk (via WkT, NT form)
    u_kernel<<<dim3(4, 8), 256>>>(wik);
    nt32<<<128, 256>>>(pu, pWkT, pt);

    // scalar score bias per (b,h)
    sbias_kernel<<<1, 256>>>();

    // scores over X (pass 1), softmax + hard threshold (writes cls weights)
    scores_kernel<<<dim3(64, 4), 256>>>(enc, mask);
    softmax_kernel<<<dim3(8, 4), 256>>>(w_out);

    // r = sum_s w * X (pass 2, partials + reduce)
    wsum_kernel<<<dim3(4, 4, 8), 256>>>(enc, w_out);
    rreduce_kernel<<<32, 256>>>();

    // p = r @ Wv^T ; attn0 = p @ wiv_h^T + sumw*bcv
    nt32<<<128, 256>>>(pr, Wv, pp);
    attn_kernel<<<128, 256>>>(wiv);

    // out_proj + residual at position 0, layernorm, classifier head
    gemv_block<<<dim3(1024, 4), 256>>>(pattn0, 1024, opw, opb, enc, 2048LL * 1024, py, 1024);
    ln_kernel<<<4, 256>>>(lng, lnb);
    gemv_block<<<dim3(1000, 4), 256>>>(pcls, 1024, fcw, fcb, nullptr, 0, out, 1024);
}